// round 14
// baseline (speedup 1.0000x reference)
#include <cuda_runtime.h>

// SoftQuantize: x (8192,512) fp32, c (4,256) fp32, sigma (1,) fp32 -> out (8192,512) fp32
// rows = 8192*128 subvectors of dim 4; softmax over 256 centers.
//
// CENTER-PAIR f32x2 packing, CENTERS SPLIT ACROSS THREAD PAIRS:
//   thread 2i   -> row i, center pairs [0,64)
//   thread 2i+1 -> row i, center pairs [64,128)
//   partial den/numerators combined with __shfl_xor_sync(...,1) at the end.
// Minimal per-thread state (~9 u64) -> high occupancy for latency hiding.
//
// Unshifted args: arg_l = k1*(z.c_l) + beta_l  (k1=2*s*log2e,
// beta_l = -s*log2e*||c_l||^2); the per-row softmax shift cancels in num/den.
// Guard: accept a row only if total den in [1e-30, 1e36]  (|num| <= ~50*den,
// so accepted numerators are finite; den is a sum of non-negatives, so ex2
// overflow -> den=inf -> rejected; NaN fails the range test). Rejected rows
// (P ~ 2.5e-4) are recomputed exactly with a scalar two-pass max fallback.
//
// c pre-scaled by k1 (cancels in ratio; undone by 1/k1 at the end).

#define LQ  256
#define NP  128             // center pairs
#define HP  64              // pairs per thread (half)
#define TPB 128
#define NROWS (8192*128)
#define DMIN 1e-30f
#define DMAX 1e36f

typedef unsigned long long u64;

static __device__ __forceinline__ u64 pk(float lo, float hi) {
    u64 r; asm("mov.b64 %0, {%1, %2};" : "=l"(r) : "f"(lo), "f"(hi)); return r;
}
static __device__ __forceinline__ void unpk(u64 v, float& lo, float& hi) {
    asm("mov.b64 {%0, %1}, %2;" : "=f"(lo), "=f"(hi) : "l"(v));
}
static __device__ __forceinline__ u64 f2fma(u64 a, u64 b, u64 c) {
    u64 d; asm("fma.rn.f32x2 %0, %1, %2, %3;" : "=l"(d) : "l"(a), "l"(b), "l"(c)); return d;
}
static __device__ __forceinline__ u64 f2add(u64 a, u64 b) {
    u64 d; asm("add.rn.f32x2 %0, %1, %2;" : "=l"(d) : "l"(a), "l"(b)); return d;
}
static __device__ __forceinline__ float ex2f(float x) {
    float y; asm("ex2.approx.f32 %0, %1;" : "=f"(y) : "f"(x)); return y;
}
static __device__ __forceinline__ float rcpf(float x) {
    float y; asm("rcp.approx.f32 %0, %1;" : "=f"(y) : "f"(x)); return y;
}

// Exact two-pass softmax for one row over ALL centers (rare tail fallback).
static __device__ __noinline__ void fb_row(const float4* __restrict__ x4,
                                           float4* __restrict__ out4,
                                           int row,
                                           const ulonglong2* scA,
                                           const ulonglong2* scB,
                                           const u64* sbb,
                                           float invk1)
{
    float4 z = x4[row];
    float m = -1.0e30f;
    for (int j = 0; j < NP; ++j) {
        const float* fA = (const float*)&scA[j];   // [0],[1]=c0 pair; [2],[3]=c1 pair
        const float* fB = (const float*)&scB[j];   // [0],[1]=c2 pair; [2],[3]=c3 pair
        const float* fb = (const float*)&sbb[j];
        #pragma unroll
        for (int h = 0; h < 2; ++h) {
            float arg = fmaf(z.x, fA[h], fb[h]);
            arg = fmaf(z.y, fA[2 + h], arg);
            arg = fmaf(z.z, fB[h], arg);
            arg = fmaf(z.w, fB[2 + h], arg);
            m = fmaxf(m, arg);
        }
    }
    float den = 0.f, n0 = 0.f, n1 = 0.f, n2 = 0.f, n3 = 0.f;
    for (int j = 0; j < NP; ++j) {
        const float* fA = (const float*)&scA[j];
        const float* fB = (const float*)&scB[j];
        const float* fb = (const float*)&sbb[j];
        #pragma unroll
        for (int h = 0; h < 2; ++h) {
            float arg = fmaf(z.x, fA[h], fb[h]);
            arg = fmaf(z.y, fA[2 + h], arg);
            arg = fmaf(z.z, fB[h], arg);
            arg = fmaf(z.w, fB[2 + h], arg);
            float p = ex2f(arg - m);
            den += p;
            n0 = fmaf(p, fA[h], n0);
            n1 = fmaf(p, fA[2 + h], n1);
            n2 = fmaf(p, fB[h], n2);
            n3 = fmaf(p, fB[2 + h], n3);
        }
    }
    float sf = rcpf(den) * invk1;
    out4[row] = make_float4(n0*sf, n1*sf, n2*sf, n3*sf);
}

__global__ __launch_bounds__(TPB, 10)
void softq_kernel(const float4* __restrict__ x4,
                  const float*  __restrict__ c,
                  const float*  __restrict__ sigma,
                  float4*       __restrict__ out4)
{
    __shared__ ulonglong2 scA[NP];  // { pk(k1c0 pair), pk(k1c1 pair) }
    __shared__ ulonglong2 scB[NP];  // { pk(k1c2 pair), pk(k1c3 pair) }
    __shared__ u64        sbb[NP];  // pk(beta pair)

    const float LOG2E = 1.4426950408889634f;
    float s  = fmaxf(sigma[0], 0.0f) + 1e-4f;
    float sl = s * LOG2E;
    float k1 = 2.0f * sl;

    int t = threadIdx.x;            // t == pair index for setup (TPB == NP)
    {
        int l0 = 2*t, l1 = 2*t + 1;
        float a0 = c[l0],        a1 = c[l1];
        float b0 = c[LQ + l0],   b1 = c[LQ + l1];
        float c0 = c[2*LQ + l0], c1 = c[2*LQ + l1];
        float d0 = c[3*LQ + l0], d1 = c[3*LQ + l1];
        float q0 = a0*a0 + b0*b0 + c0*c0 + d0*d0;
        float q1 = a1*a1 + b1*b1 + c1*c1 + d1*d1;
        scA[t].x = pk(k1*a0, k1*a1);
        scA[t].y = pk(k1*b0, k1*b1);
        scB[t].x = pk(k1*c0, k1*c1);
        scB[t].y = pk(k1*d0, k1*d1);
        sbb[t]   = pk(-sl*q0, -sl*q1);
    }
    __syncthreads();

    const int half = t & 1;                              // which 64 center pairs
    const int row  = blockIdx.x * (TPB / 2) + (t >> 1);  // one row per thread pair

    // zz[m] = pk(z_m, z_m): row components duplicated across the f32x2 lanes
    u64 zz0, zz1, zz2, zz3;
    {
        float4 z = x4[row];
        zz0 = pk(z.x, z.x);
        zz1 = pk(z.y, z.y);
        zz2 = pk(z.z, z.z);
        zz3 = pk(z.w, z.w);
    }

    u64 den2 = 0ull;
    u64 nn0 = 0ull, nn1 = 0ull, nn2 = 0ull, nn3 = 0ull;

    const int jbase = half * HP;
    #pragma unroll 4
    for (int jj = 0; jj < HP; ++jj) {
        int j = jbase + jj;
        ulonglong2 cA = scA[j];
        ulonglong2 cB = scB[j];
        u64 bb = sbb[j];
        u64 d = f2fma(zz0, cA.x, bb);    // beta pair seeds the chain
        d     = f2fma(zz1, cA.y, d);
        d     = f2fma(zz2, cB.x, d);
        d     = f2fma(zz3, cB.y, d);
        float aL, aH; unpk(d, aL, aH);
        u64 pp = pk(ex2f(aL), ex2f(aH));
        den2 = f2add(den2, pp);
        nn0  = f2fma(pp, cA.x, nn0);
        nn1  = f2fma(pp, cA.y, nn1);
        nn2  = f2fma(pp, cB.x, nn2);
        nn3  = f2fma(pp, cB.y, nn3);
    }

    // ---- cross-thread combine (lanes 2i <-> 2i+1 share a warp) ----
    den2 = f2add(den2, __shfl_xor_sync(0xffffffffu, den2, 1));
    nn0  = f2add(nn0,  __shfl_xor_sync(0xffffffffu, nn0,  1));
    nn1  = f2add(nn1,  __shfl_xor_sync(0xffffffffu, nn1,  1));
    nn2  = f2add(nn2,  __shfl_xor_sync(0xffffffffu, nn2,  1));
    nn3  = f2add(nn3,  __shfl_xor_sync(0xffffffffu, nn3,  1));

    // ---- even lane: horizontal combine (even+odd centers), guard, divide ----
    if (half == 0) {
        float invk1 = 1.0f / k1;
        float dL, dH; unpk(den2, dL, dH);
        float den = dL + dH;
        if (!((den >= DMIN) && (den <= DMAX))) {        // NaN/inf fail too
            fb_row(x4, out4, row, scA, scB, sbb, invk1);
        } else {
            float sf = rcpf(den) * invk1;
            float n0l, n0h, n1l, n1h, n2l, n2h, n3l, n3h;
            unpk(nn0, n0l, n0h);
            unpk(nn1, n1l, n1h);
            unpk(nn2, n2l, n2h);
            unpk(nn3, n3l, n3h);
            out4[row] = make_float4((n0l + n0h) * sf, (n1l + n1h) * sf,
                                    (n2l + n2h) * sf, (n3l + n3h) * sf);
        }
    }
}

extern "C" void kernel_launch(void* const* d_in, const int* in_sizes, int n_in,
                              void* d_out, int out_size)
{
    const float* x     = (const float*)d_in[0];
    const float* c     = (const float*)d_in[1];
    const float* sigma = (const float*)d_in[2];
    float* out = (float*)d_out;

    int blocks = NROWS / (TPB / 2);   // 16384
    softq_kernel<<<blocks, TPB>>>((const float4*)x, c, sigma, (float4*)out);
}

// round 15
// speedup vs baseline: 1.2623x; 1.2623x over previous
#include <cuda_runtime.h>

// SoftQuantize: x (8192,512) fp32, c (4,256) fp32, sigma (1,) fp32 -> out (8192,512) fp32
// rows = 8192*128 subvectors of dim 4; softmax over 256 centers.
//
// CENTER-PAIR f32x2 packing, TWO ROWS PER THREAD (R13 shape), register-capped
// to 56 (__launch_bounds__(128,9)) for 9 blocks/SM = 36 resident warps:
//   f32x2 lanes = centers (2j, 2j+1); den/numerators are even/odd-center
//   partial sums, combined horizontally at the end. Two independent
//   dot->ex2->accumulate chains per iteration share one set of broadcast
//   codebook LDS loads (10 bytes of shared traffic per element).
//
// Unshifted args: arg_l = k1*(z.c_l) + beta_l  (k1=2*s*log2e,
// beta_l = -s*log2e*||c_l||^2); the per-row softmax shift cancels in num/den.
// Guard: accept a row only if total den in [1e-30, 1e36]  (|num| <= ~50*den,
// so accepted numerators are finite; den is a sum of non-negatives, so ex2
// overflow -> den=inf -> rejected; NaN fails the range test). Rejected rows
// (P ~ 2.5e-4) are recomputed exactly with a scalar two-pass max fallback.
//
// c pre-scaled by k1 (cancels in ratio; undone by 1/k1 at the end).

#define LQ  256
#define NP  128             // center pairs
#define TPB 128
#define NROWS (8192*128)
#define DMIN 1e-30f
#define DMAX 1e36f

typedef unsigned long long u64;

static __device__ __forceinline__ u64 pk(float lo, float hi) {
    u64 r; asm("mov.b64 %0, {%1, %2};" : "=l"(r) : "f"(lo), "f"(hi)); return r;
}
static __device__ __forceinline__ void unpk(u64 v, float& lo, float& hi) {
    asm("mov.b64 {%0, %1}, %2;" : "=f"(lo), "=f"(hi) : "l"(v));
}
static __device__ __forceinline__ u64 f2fma(u64 a, u64 b, u64 c) {
    u64 d; asm("fma.rn.f32x2 %0, %1, %2, %3;" : "=l"(d) : "l"(a), "l"(b), "l"(c)); return d;
}
static __device__ __forceinline__ u64 f2add(u64 a, u64 b) {
    u64 d; asm("add.rn.f32x2 %0, %1, %2;" : "=l"(d) : "l"(a), "l"(b)); return d;
}
static __device__ __forceinline__ float ex2f(float x) {
    float y; asm("ex2.approx.f32 %0, %1;" : "=f"(y) : "f"(x)); return y;
}
static __device__ __forceinline__ float rcpf(float x) {
    float y; asm("rcp.approx.f32 %0, %1;" : "=f"(y) : "f"(x)); return y;
}

// Exact two-pass softmax for one row (rare tail fallback).
// scA[j] = { pk(k1c0[2j],k1c0[2j+1]), pk(k1c1[2j],k1c1[2j+1]) }
// scB[j] = { pk(k1c2...),             pk(k1c3...) },  sbb[j] = pk(b[2j],b[2j+1])
static __device__ __noinline__ void fb_row(const float4* __restrict__ x4,
                                           float4* __restrict__ out4,
                                           int row,
                                           const ulonglong2* scA,
                                           const ulonglong2* scB,
                                           const u64* sbb,
                                           float invk1)
{
    float4 z = x4[row];
    float m = -1.0e30f;
    for (int j = 0; j < NP; ++j) {
        const float* fA = (const float*)&scA[j];   // [0],[1]=c0 pair; [2],[3]=c1 pair
        const float* fB = (const float*)&scB[j];   // [0],[1]=c2 pair; [2],[3]=c3 pair
        const float* fb = (const float*)&sbb[j];
        #pragma unroll
        for (int h = 0; h < 2; ++h) {
            float arg = fmaf(z.x, fA[h], fb[h]);
            arg = fmaf(z.y, fA[2 + h], arg);
            arg = fmaf(z.z, fB[h], arg);
            arg = fmaf(z.w, fB[2 + h], arg);
            m = fmaxf(m, arg);
        }
    }
    float den = 0.f, n0 = 0.f, n1 = 0.f, n2 = 0.f, n3 = 0.f;
    for (int j = 0; j < NP; ++j) {
        const float* fA = (const float*)&scA[j];
        const float* fB = (const float*)&scB[j];
        const float* fb = (const float*)&sbb[j];
        #pragma unroll
        for (int h = 0; h < 2; ++h) {
            float arg = fmaf(z.x, fA[h], fb[h]);
            arg = fmaf(z.y, fA[2 + h], arg);
            arg = fmaf(z.z, fB[h], arg);
            arg = fmaf(z.w, fB[2 + h], arg);
            float p = ex2f(arg - m);
            den += p;
            n0 = fmaf(p, fA[h], n0);
            n1 = fmaf(p, fA[2 + h], n1);
            n2 = fmaf(p, fB[h], n2);
            n3 = fmaf(p, fB[2 + h], n3);
        }
    }
    float sf = rcpf(den) * invk1;
    out4[row] = make_float4(n0*sf, n1*sf, n2*sf, n3*sf);
}

__global__ __launch_bounds__(TPB, 9)
void softq_kernel(const float4* __restrict__ x4,
                  const float*  __restrict__ c,
                  const float*  __restrict__ sigma,
                  float4*       __restrict__ out4)
{
    __shared__ ulonglong2 scA[NP];  // { pk(k1c0 pair), pk(k1c1 pair) }
    __shared__ ulonglong2 scB[NP];  // { pk(k1c2 pair), pk(k1c3 pair) }
    __shared__ u64        sbb[NP];  // pk(beta pair)

    const float LOG2E = 1.4426950408889634f;
    float s  = fmaxf(sigma[0], 0.0f) + 1e-4f;
    float sl = s * LOG2E;
    float k1 = 2.0f * sl;

    int t = threadIdx.x;            // t == pair index j for setup (TPB == NP)
    {
        int l0 = 2*t, l1 = 2*t + 1;
        float a0 = c[l0],        a1 = c[l1];
        float b0 = c[LQ + l0],   b1 = c[LQ + l1];
        float c0 = c[2*LQ + l0], c1 = c[2*LQ + l1];
        float d0 = c[3*LQ + l0], d1 = c[3*LQ + l1];
        float q0 = a0*a0 + b0*b0 + c0*c0 + d0*d0;
        float q1 = a1*a1 + b1*b1 + c1*c1 + d1*d1;
        scA[t].x = pk(k1*a0, k1*a1);
        scA[t].y = pk(k1*b0, k1*b1);
        scB[t].x = pk(k1*c0, k1*c1);
        scB[t].y = pk(k1*d0, k1*d1);
        sbb[t]   = pk(-sl*q0, -sl*q1);
    }
    __syncthreads();

    const int rowA = blockIdx.x * (2 * TPB) + t;   // two rows per thread
    const int rowB = rowA + TPB;

    // zz?[m] = pk(z_m, z_m): row components duplicated across the f32x2 lanes
    u64 zA0, zA1, zA2, zA3, zB0, zB1, zB2, zB3;
    {
        float4 za = x4[rowA];
        float4 zb = x4[rowB];
        zA0 = pk(za.x, za.x); zA1 = pk(za.y, za.y);
        zA2 = pk(za.z, za.z); zA3 = pk(za.w, za.w);
        zB0 = pk(zb.x, zb.x); zB1 = pk(zb.y, zb.y);
        zB2 = pk(zb.z, zb.z); zB3 = pk(zb.w, zb.w);
    }

    u64 denA = 0ull, nA0 = 0ull, nA1 = 0ull, nA2 = 0ull, nA3 = 0ull;
    u64 denB = 0ull, nB0 = 0ull, nB1 = 0ull, nB2 = 0ull, nB3 = 0ull;

    #pragma unroll 2
    for (int j = 0; j < NP; ++j) {
        ulonglong2 cA = scA[j];
        ulonglong2 cB = scB[j];
        u64 bb = sbb[j];

        // two independent chains share the codebook registers
        u64 dA = f2fma(zA0, cA.x, bb);
        u64 dB = f2fma(zB0, cA.x, bb);
        dA     = f2fma(zA1, cA.y, dA);
        dB     = f2fma(zB1, cA.y, dB);
        dA     = f2fma(zA2, cB.x, dA);
        dB     = f2fma(zB2, cB.x, dB);
        dA     = f2fma(zA3, cB.y, dA);
        dB     = f2fma(zB3, cB.y, dB);

        float aL, aH, bL, bH;
        unpk(dA, aL, aH);
        unpk(dB, bL, bH);
        u64 ppA = pk(ex2f(aL), ex2f(aH));
        u64 ppB = pk(ex2f(bL), ex2f(bH));

        denA = f2add(denA, ppA);
        denB = f2add(denB, ppB);
        nA0  = f2fma(ppA, cA.x, nA0);
        nB0  = f2fma(ppB, cA.x, nB0);
        nA1  = f2fma(ppA, cA.y, nA1);
        nB1  = f2fma(ppB, cA.y, nB1);
        nA2  = f2fma(ppA, cB.x, nA2);
        nB2  = f2fma(ppB, cB.x, nB2);
        nA3  = f2fma(ppA, cB.y, nA3);
        nB3  = f2fma(ppB, cB.y, nB3);
    }

    // ---- horizontal combine (even+odd centers), guard, divide ----
    float invk1 = 1.0f / k1;
    {
        float dL, dH; unpk(denA, dL, dH);
        float den = dL + dH;
        if (!((den >= DMIN) && (den <= DMAX))) {       // NaN/inf fail too
            fb_row(x4, out4, rowA, scA, scB, sbb, invk1);
        } else {
            float sf = rcpf(den) * invk1;
            float n0l, n0h, n1l, n1h, n2l, n2h, n3l, n3h;
            unpk(nA0, n0l, n0h);
            unpk(nA1, n1l, n1h);
            unpk(nA2, n2l, n2h);
            unpk(nA3, n3l, n3h);
            out4[rowA] = make_float4((n0l + n0h) * sf, (n1l + n1h) * sf,
                                     (n2l + n2h) * sf, (n3l + n3h) * sf);
        }
    }
    {
        float dL, dH; unpk(denB, dL, dH);
        float den = dL + dH;
        if (!((den >= DMIN) && (den <= DMAX))) {
            fb_row(x4, out4, rowB, scA, scB, sbb, invk1);
        } else {
            float sf = rcpf(den) * invk1;
            float n0l, n0h, n1l, n1h, n2l, n2h, n3l, n3h;
            unpk(nB0, n0l, n0h);
            unpk(nB1, n1l, n1h);
            unpk(nB2, n2l, n2h);
            unpk(nB3, n3l, n3h);
            out4[rowB] = make_float4((n0l + n0h) * sf, (n1l + n1h) * sf,
                                     (n2l + n2h) * sf, (n3l + n3h) * sf);
        }
    }
}

extern "C" void kernel_launch(void* const* d_in, const int* in_sizes, int n_in,
                              void* d_out, int out_size)
{
    const float* x     = (const float*)d_in[0];
    const float* c     = (const float*)d_in[1];
    const float* sigma = (const float*)d_in[2];
    float* out = (float*)d_out;

    int blocks = NROWS / (2 * TPB);   // 4096
    softq_kernel<<<blocks, TPB>>>((const float4*)x, c, sigma, (float4*)out);
}